// round 6
// baseline (speedup 1.0000x reference)
#include <cuda_runtime.h>

// Bilinear 2x upsample NHWC f32: (8,256,256,32) -> (8,512,512,32).
// Dual-quad kernel: each thread produces a 2x4 output region (two vertically
// adjacent 2x2 quads) from a 3x2 input patch (per float4 channel group).
// Quads 2k and 2k+1 share input row k -> 6 loads per 8 stores.
// Fixed fractions for scale 0.5; edges handled by clamping (degenerate
// patches have equal loaded values -> duplicate writes are exact).

#define IH 256
#define IW 256
#define OH 512
#define OW 512
#define C4 8          // 32 channels / 4 floats

__device__ __forceinline__ void stcs4(float4* p, float4 v) {
    __stcs(p, v);
}

__global__ __launch_bounds__(256) void bilinear2x_dualquad_kernel(
    const float4* __restrict__ in, float4* __restrict__ out)
{
    // threadIdx.x: [jloc:5][c4:3] -> 32 x-quads x 8 channel-groups per block
    const int c4 = threadIdx.x & (C4 - 1);
    const int j  = blockIdx.x * 32 + (threadIdx.x >> 3);   // x-quad index, 0..256
    if (j > IW) return;                                     // 257 quads in x
    const int k0 = blockIdx.y * 2;                          // first y-quad (0..256)
    const int n  = blockIdx.z;
    const bool has_k1 = (k0 < IH);                          // second quad valid iff k0+1 <= 256

    // Input columns (clamped)
    const int xa = max(j - 1, 0);
    const int xb = min(j, IW - 1);
    // Input rows: ra/rb for quad k0, rb/rc for quad k0+1
    const int ra = max(k0 - 1, 0);
    const int rb = min(k0, IH - 1);
    const int rc = min(k0 + 1, IH - 1);

    const float4* __restrict__ ibase = in + (long long)n * (IH * IW * C4);
    const float4 va0 = __ldg(ibase + (ra * IW + xa) * C4 + c4);
    const float4 va1 = __ldg(ibase + (ra * IW + xb) * C4 + c4);
    const float4 vb0 = __ldg(ibase + (rb * IW + xa) * C4 + c4);
    const float4 vb1 = __ldg(ibase + (rb * IW + xb) * C4 + c4);
    const float4 vc0 = __ldg(ibase + (rc * IW + xa) * C4 + c4);
    const float4 vc1 = __ldg(ibase + (rc * IW + xb) * C4 + c4);

    // x-interpolation per input row: L (left out col, w_right=0.25), R (w_right=0.75)
    float4 aL, aR, bL, bR, cL, cR;
    #define XI(L, R, v0, v1) \
        L.x = 0.75f*v0.x + 0.25f*v1.x;  R.x = 0.25f*v0.x + 0.75f*v1.x; \
        L.y = 0.75f*v0.y + 0.25f*v1.y;  R.y = 0.25f*v0.y + 0.75f*v1.y; \
        L.z = 0.75f*v0.z + 0.25f*v1.z;  R.z = 0.25f*v0.z + 0.75f*v1.z; \
        L.w = 0.75f*v0.w + 0.25f*v1.w;  R.w = 0.25f*v0.w + 0.75f*v1.w;
    XI(aL, aR, va0, va1)
    XI(bL, bR, vb0, vb1)
    XI(cL, cR, vc0, vc1)
    #undef XI

    // Output columns (clamped)
    const int c0 = max(2 * j - 1, 0);
    const int c1 = min(2 * j, OW - 1);
    float4* __restrict__ obase = out + (long long)n * (OH * OW * C4);

    #define YI(o, T, B, wt, wb) \
        o.x = wt*T.x + wb*B.x; o.y = wt*T.y + wb*B.y; \
        o.z = wt*T.z + wb*B.z; o.w = wt*T.w + wb*B.w;

    float4 o;
    // Quad k0: rows r0 = max(2k0-1,0), r1 = min(2k0,511)
    {
        const int r0 = max(2 * k0 - 1, 0);
        const int r1 = min(2 * k0, OH - 1);
        YI(o, aL, bL, 0.75f, 0.25f)  stcs4(obase + (r0 * OW + c0) * C4 + c4, o);
        YI(o, aR, bR, 0.75f, 0.25f)  stcs4(obase + (r0 * OW + c1) * C4 + c4, o);
        YI(o, aL, bL, 0.25f, 0.75f)  stcs4(obase + (r1 * OW + c0) * C4 + c4, o);
        YI(o, aR, bR, 0.25f, 0.75f)  stcs4(obase + (r1 * OW + c1) * C4 + c4, o);
    }
    // Quad k0+1: rows r2 = 2k0+1, r3 = min(2k0+2,511)
    if (has_k1) {
        const int r2 = 2 * k0 + 1;
        const int r3 = min(2 * k0 + 2, OH - 1);
        YI(o, bL, cL, 0.75f, 0.25f)  stcs4(obase + (r2 * OW + c0) * C4 + c4, o);
        YI(o, bR, cR, 0.75f, 0.25f)  stcs4(obase + (r2 * OW + c1) * C4 + c4, o);
        YI(o, bL, cL, 0.25f, 0.75f)  stcs4(obase + (r3 * OW + c0) * C4 + c4, o);
        YI(o, bR, cR, 0.25f, 0.75f)  stcs4(obase + (r3 * OW + c1) * C4 + c4, o);
    }
    #undef YI
}

extern "C" void kernel_launch(void* const* d_in, const int* in_sizes, int n_in,
                              void* d_out, int out_size)
{
    const float4* in  = (const float4*)d_in[0];
    float4*       out = (float4*)d_out;
    // 257 x-quads; 129 y-quad pairs (last pair degenerate: only quad 256)
    dim3 block(256, 1, 1);                 // 32 j x 8 c4
    dim3 grid((IW / 32) + 1, IH / 2 + 1, 8);  // (9, 129, 8)
    bilinear2x_dualquad_kernel<<<grid, block>>>(in, out);
}

// round 7
// speedup vs baseline: 1.0184x; 1.0184x over previous
#include <cuda_runtime.h>

// Bilinear 2x upsample NHWC f32: (8,256,256,32) -> (8,512,512,32).
// Single-quad kernel (best occupancy/e2e shape) + __stcs evict-first stores:
// the 268MB output stream is never reused, so bias L2 to keep the 67MB input
// resident (input then stays L2-hot across graph replays).
// Each thread: one 2x2 output quad from one 2x2 input patch per float4
// channel group. Fixed fractions for scale 0.5; edges via clamping
// (degenerate patches have equal loaded values -> duplicate writes exact).

#define IH 256
#define IW 256
#define OH 512
#define OW 512
#define C4 8          // 32 channels / 4 floats

__global__ __launch_bounds__(256) void bilinear2x_quad_stcs_kernel(
    const float4* __restrict__ in, float4* __restrict__ out)
{
    // threadIdx.x: [jloc:5][c4:3] -> 32 x-quads x 8 channel-groups per block
    const int c4 = threadIdx.x & (C4 - 1);
    const int j  = blockIdx.x * 32 + (threadIdx.x >> 3);   // x-quad index, 0..256
    if (j > IW) return;                                     // 257 quads in x
    const int k  = blockIdx.y;                              // y-quad index, 0..256
    const int n  = blockIdx.z;

    // Input patch coords (clamped)
    const int ya = max(k - 1, 0);
    const int yb = min(k, IH - 1);
    const int xa = max(j - 1, 0);
    const int xb = min(j, IW - 1);

    const float4* __restrict__ ibase = in + (long long)n * (IH * IW * C4);
    const float4 vaa = __ldg(ibase + (ya * IW + xa) * C4 + c4);
    const float4 vab = __ldg(ibase + (ya * IW + xb) * C4 + c4);
    const float4 vba = __ldg(ibase + (yb * IW + xa) * C4 + c4);
    const float4 vbb = __ldg(ibase + (yb * IW + xb) * C4 + c4);

    // Separable x-interps: w_right = 0.25 for left out col, 0.75 for right
    float4 tL, tR, bL, bR;
    tL.x = 0.75f * vaa.x + 0.25f * vab.x;  tR.x = 0.25f * vaa.x + 0.75f * vab.x;
    tL.y = 0.75f * vaa.y + 0.25f * vab.y;  tR.y = 0.25f * vaa.y + 0.75f * vab.y;
    tL.z = 0.75f * vaa.z + 0.25f * vab.z;  tR.z = 0.25f * vaa.z + 0.75f * vab.z;
    tL.w = 0.75f * vaa.w + 0.25f * vab.w;  tR.w = 0.25f * vaa.w + 0.75f * vab.w;
    bL.x = 0.75f * vba.x + 0.25f * vbb.x;  bR.x = 0.25f * vba.x + 0.75f * vbb.x;
    bL.y = 0.75f * vba.y + 0.25f * vbb.y;  bR.y = 0.25f * vba.y + 0.75f * vbb.y;
    bL.z = 0.75f * vba.z + 0.25f * vbb.z;  bR.z = 0.25f * vba.z + 0.75f * vbb.z;
    bL.w = 0.75f * vba.w + 0.25f * vbb.w;  bR.w = 0.25f * vba.w + 0.75f * vbb.w;

    // Output quad coords (clamped; edge duplicates write the same value)
    const int r0 = max(2 * k - 1, 0);
    const int r1 = min(2 * k, OH - 1);
    const int c0 = max(2 * j - 1, 0);
    const int c1 = min(2 * j, OW - 1);

    float4* __restrict__ obase = out + (long long)n * (OH * OW * C4);

    float4 o;
    // (r0, c0): bottom weight 0.25
    o.x = 0.75f * tL.x + 0.25f * bL.x;
    o.y = 0.75f * tL.y + 0.25f * bL.y;
    o.z = 0.75f * tL.z + 0.25f * bL.z;
    o.w = 0.75f * tL.w + 0.25f * bL.w;
    __stcs(obase + (r0 * OW + c0) * C4 + c4, o);

    // (r0, c1)
    o.x = 0.75f * tR.x + 0.25f * bR.x;
    o.y = 0.75f * tR.y + 0.25f * bR.y;
    o.z = 0.75f * tR.z + 0.25f * bR.z;
    o.w = 0.75f * tR.w + 0.25f * bR.w;
    __stcs(obase + (r0 * OW + c1) * C4 + c4, o);

    // (r1, c0): bottom weight 0.75
    o.x = 0.25f * tL.x + 0.75f * bL.x;
    o.y = 0.25f * tL.y + 0.75f * bL.y;
    o.z = 0.25f * tL.z + 0.75f * bL.z;
    o.w = 0.25f * tL.w + 0.75f * bL.w;
    __stcs(obase + (r1 * OW + c0) * C4 + c4, o);

    // (r1, c1)
    o.x = 0.25f * tR.x + 0.75f * bR.x;
    o.y = 0.25f * tR.y + 0.75f * bR.y;
    o.z = 0.25f * tR.z + 0.75f * bR.z;
    o.w = 0.25f * tR.w + 0.75f * bR.w;
    __stcs(obase + (r1 * OW + c1) * C4 + c4, o);
}

extern "C" void kernel_launch(void* const* d_in, const int* in_sizes, int n_in,
                              void* d_out, int out_size)
{
    const float4* in  = (const float4*)d_in[0];
    float4*       out = (float4*)d_out;
    dim3 block(256, 1, 1);                    // 32 j x 8 c4
    dim3 grid((IW / 32) + 1, IH + 1, 8);      // (9, 257, 8)
    bilinear2x_quad_stcs_kernel<<<grid, block>>>(in, out);
}